// round 14
// baseline (speedup 1.0000x reference)
#include <cuda_runtime.h>

#define B_    2
#define N_    512
#define E_    768
#define H_    48
#define D_    16
#define NEXP_ 256
#define M_    768
#define LOG2E 1.4426950408889634f

typedef unsigned long long ull;

__device__ __forceinline__ ull pk2(float lo, float hi){ ull r; asm("mov.b64 %0,{%1,%2};":"=l"(r):"f"(lo),"f"(hi)); return r; }
__device__ __forceinline__ void upk2(float&lo,float&hi,ull v){ asm("mov.b64 {%0,%1},%2;":"=f"(lo),"=f"(hi):"l"(v)); }
__device__ __forceinline__ ull fma2_(ull a, ull b, ull c){ ull d; asm("fma.rn.f32x2 %0,%1,%2,%3;":"=l"(d):"l"(a),"l"(b),"l"(c)); return d; }
__device__ __forceinline__ ull add2_(ull a, ull b){ ull d; asm("add.rn.f32x2 %0,%1,%2;":"=l"(d):"l"(a),"l"(b)); return d; }
__device__ __forceinline__ ull mul2_(ull a, ull b){ ull d; asm("mul.rn.f32x2 %0,%1,%2;":"=l"(d):"l"(a),"l"(b)); return d; }
__device__ __forceinline__ float ex2_(float x){ float r; asm("ex2.approx.f32 %0,%1;":"=f"(r):"f"(x)); return r; }

// ---------------- device scratch ----------------
__device__ float g_Q[B_*N_*E_];          // Q proj, pre-scaled by 0.25*log2e
__device__ float g_K[B_*N_*E_];          // K proj
__device__ float g_VW[B_*N_*H_];         // v . w_force per head  [row][48]
__device__ float g_Wveff[H_*E_];
__device__ float g_beff[H_];
__device__ float g_part[12*2*B_*N_*16];  // [g][ms][b][n][hh][4]: den,A0,A1,A2

// ---------------- kernel 1: fold Wv with w_force ----------------
__global__ void wveff_kernel(const float* __restrict__ Wv,
                             const float* __restrict__ bv,
                             const float* __restrict__ wf)
{
    int h = blockIdx.x, e = threadIdx.x;
    float sv = 0.f;
#pragma unroll
    for (int dd = 0; dd < 16; dd++)
        sv = fmaf(wf[h*16+dd], Wv[(h*16+dd)*E_ + e], sv);
    g_Wveff[h*E_ + e] = sv;
    if (e == 0) {
        float bb = 0.f;
#pragma unroll
        for (int dd = 0; dd < 16; dd++)
            bb = fmaf(wf[h*16+dd], bv[h*16+dd], bb);
        g_beff[h] = bb;
    }
}

// ---------------- kernel 2: fused Q+K projection GEMM (round-6, PASSED) ----------------
// Tile 64 rows x 128 cols, 256 threads, micro 4 rows x 4 col-pairs, double-buffered.
__global__ __launch_bounds__(256,2) void qk_gemm(
    const float* __restrict__ A,
    const float* __restrict__ Wq, const float* __restrict__ bq,
    const float* __restrict__ Wk, const float* __restrict__ bk)
{
    __shared__ ull   Asd[2][16*64];    // [k][row], duplicated (a,a)
    __shared__ float Bs[2][16*132];    // [k][col], pad 132

    int t  = threadIdx.x;
    int tx = t & 15, ty = t >> 4;
    int row0 = blockIdx.y * 64;
    int col0 = blockIdx.x * 128;

    const float* __restrict__ W; const float* __restrict__ bvec;
    float scale; float* C; int cb;
    if (col0 < E_) { W = Wq; bvec = bq; scale = 0.25f*LOG2E; C = g_Q; cb = col0; }
    else           { W = Wk; bvec = bk; scale = 1.0f;        C = g_K; cb = col0 - E_; }

    int arow = t >> 2;            // 0..63
    int akq  = (t & 3) * 4;       // k offset
    const float* Aptr = A + (row0 + arow)*E_ + akq;
    int bc0 = t >> 2,        bk0 = (t & 3)*4;
    int bc1 = (256+t) >> 2,  bk1 = ((256+t) & 3)*4;
    const float* Bptr0 = W + (cb + bc0)*E_ + bk0;
    const float* Bptr1 = W + (cb + bc1)*E_ + bk1;

    ull acc[4][4];
#pragma unroll
    for (int r = 0; r < 4; r++)
#pragma unroll
        for (int j = 0; j < 4; j++) acc[r][j] = 0ull;

    // prologue: stage k0 = 0 into buf 0
    {
        float4 va = *(const float4*)(Aptr);
        Asd[0][(akq+0)*64+arow] = pk2(va.x,va.x);
        Asd[0][(akq+1)*64+arow] = pk2(va.y,va.y);
        Asd[0][(akq+2)*64+arow] = pk2(va.z,va.z);
        Asd[0][(akq+3)*64+arow] = pk2(va.w,va.w);
        float4 vb = *(const float4*)(Bptr0);
        Bs[0][(bk0+0)*132+bc0] = vb.x; Bs[0][(bk0+1)*132+bc0] = vb.y;
        Bs[0][(bk0+2)*132+bc0] = vb.z; Bs[0][(bk0+3)*132+bc0] = vb.w;
        float4 vc = *(const float4*)(Bptr1);
        Bs[0][(bk1+0)*132+bc1] = vc.x; Bs[0][(bk1+1)*132+bc1] = vc.y;
        Bs[0][(bk1+2)*132+bc1] = vc.z; Bs[0][(bk1+3)*132+bc1] = vc.w;
    }
    __syncthreads();

    for (int s = 0; s < 48; s++) {
        int buf = s & 1;
        float4 pa, pb, pc;
        if (s < 47) {
            int k0 = (s+1)*16;
            pa = *(const float4*)(Aptr + k0);
            pb = *(const float4*)(Bptr0 + k0);
            pc = *(const float4*)(Bptr1 + k0);
        }
#pragma unroll
        for (int k = 0; k < 16; k++) {
            ull a2[4];
#pragma unroll
            for (int r = 0; r < 4; r++) a2[r] = Asd[buf][k*64 + ty*4 + r];
            const ull* bp = (const ull*)&Bs[buf][k*132];
            ull b2[4];
#pragma unroll
            for (int jp = 0; jp < 4; jp++) b2[jp] = bp[tx + 16*jp];
#pragma unroll
            for (int r = 0; r < 4; r++)
#pragma unroll
                for (int jp = 0; jp < 4; jp++)
                    acc[r][jp] = fma2_(a2[r], b2[jp], acc[r][jp]);
        }
        if (s < 47) {
            int nb = buf ^ 1;
            Asd[nb][(akq+0)*64+arow] = pk2(pa.x,pa.x);
            Asd[nb][(akq+1)*64+arow] = pk2(pa.y,pa.y);
            Asd[nb][(akq+2)*64+arow] = pk2(pa.z,pa.z);
            Asd[nb][(akq+3)*64+arow] = pk2(pa.w,pa.w);
            Bs[nb][(bk0+0)*132+bc0] = pb.x; Bs[nb][(bk0+1)*132+bc0] = pb.y;
            Bs[nb][(bk0+2)*132+bc0] = pb.z; Bs[nb][(bk0+3)*132+bc0] = pb.w;
            Bs[nb][(bk1+0)*132+bc1] = pc.x; Bs[nb][(bk1+1)*132+bc1] = pc.y;
            Bs[nb][(bk1+2)*132+bc1] = pc.z; Bs[nb][(bk1+3)*132+bc1] = pc.w;
        }
        __syncthreads();
    }

#pragma unroll
    for (int r = 0; r < 4; r++) {
        int row = row0 + ty*4 + r;
#pragma unroll
        for (int jp = 0; jp < 4; jp++) {
            int c0 = cb + 2*(tx + 16*jp);
            float v0, v1; upk2(v0, v1, acc[r][jp]);
            float2 o = make_float2(scale*(v0 + bvec[c0]), scale*(v1 + bvec[c0+1]));
            *(float2*)(C + row*E_ + c0) = o;
        }
    }
}

// ---------------- kernel 3: vw = query @ Wv_eff^T + b_eff (round-5/6, PASSED) ----------------
__global__ __launch_bounds__(768) void vw_kernel(const float* __restrict__ query)
{
    __shared__ float qrow[E_];
    int row = blockIdx.x;
    qrow[threadIdx.x] = query[row*E_ + threadIdx.x];
    __syncthreads();
    int h = threadIdx.x >> 4, lane = threadIdx.x & 15;
    const float* __restrict__ wv = &g_Wveff[h*E_];
    float sacc = 0.f;
#pragma unroll 8
    for (int j = lane; j < E_; j += 16) sacc = fmaf(qrow[j], wv[j], sacc);
#pragma unroll
    for (int o = 8; o > 0; o >>= 1) sacc += __shfl_down_sync(0xffffffffu, sacc, o, 16);
    if (lane == 0) g_VW[row*H_ + h] = sacc + g_beff[h];
}

// ---------------- kernel 4: fused attention (m-packed f32x2, alignment-safe smem) ----------------
// grid (12 hg, 32 ntile(16 rows), b*2+ms).  256 threads: h=t&3, nr=(t>>2)&15, s=t>>6.
// Thread: 1 n-row x 4 m-cols (2 packed m-pairs) per 16-chunk; 24 chunks.
__global__ __launch_bounds__(256,2) void attn_kernel(
    const float* __restrict__ bias, const float* __restrict__ dp,
    const int*   __restrict__ outcell)
{
    __shared__ float4 sK4[4*65];         // floats: [h][d][mc], h-stride 260, d-stride 16
    __shared__ float4 sVW4[4*5];         // floats: [h][mc], h-stride 20
    __shared__ float4 sDP4[3*80];        // floats: [c][nn][mc], c-stride 320, nn-stride 20
    __shared__ float  scomb[4][4][16][4];// [s][h][nr][val]

    float* sKf  = (float*)sK4;
    float* sVWf = (float*)sVW4;
    float* sDPf = (float*)sDP4;

    int t  = threadIdx.x;
    int h  = t & 3;
    int nr = (t >> 2) & 15;
    int s  = t >> 6;
    int g  = blockIdx.x;
    int h0 = g * 4;
    int n0 = blockIdx.y * 16;
    int bz = blockIdx.z;
    int b  = bz >> 1, ms = bz & 1;
    const int* __restrict__ oc = outcell + b*NEXP_;
    int n = n0 + nr;

    // Q duplicated in registers (loop-invariant). Pre-scaled by 0.25*log2e.
    ull q2[16];
    {
        const float4* qp = (const float4*)&g_Q[(size_t)(b*N_ + n)*E_ + (h0+h)*D_];
#pragma unroll
        for (int i = 0; i < 4; i++) {
            float4 v = qp[i];
            q2[4*i+0] = pk2(v.x,v.x); q2[4*i+1] = pk2(v.y,v.y);
            q2[4*i+2] = pk2(v.z,v.z); q2[4*i+3] = pk2(v.w,v.w);
        }
    }

    const float* bptr = bias + (size_t)(b*H_ + h0 + h)*(N_*M_) + (size_t)n*M_ + ms*384 + s*4;
    int mcs = t >> 4, q4 = t & 15;
    int khh = q4 >> 2, kdg = (q4 & 3)*4;
    const ull L2E2 = pk2(LOG2E, LOG2E);

    ull den = 0ull, Ac0 = 0ull, Ac1 = 0ull, Ac2 = 0ull;

    float4 pb = *(const float4*)bptr;    // bias prefetch (chunk 0)

#pragma unroll 1
    for (int ch = 0; ch < 24; ch++) {
        int m0 = ms*384 + ch*16;
        float4 cbias = pb;
        if (ch < 23) pb = *(const float4*)(bptr + (ch+1)*16);

        __syncthreads();
        // --- stage K transposed (gathered): sKf[h*260 + d*16 + mc] ---
        {
            int m = m0 + mcs;
            int r = (m < N_) ? m : oc[m - N_];
            float4 v = *(const float4*)&g_K[(size_t)(b*N_ + r)*E_ + (h0+khh)*D_ + kdg];
            float* dst = &sKf[khh*260 + kdg*16 + mcs];
            dst[0] = v.x; dst[16] = v.y; dst[32] = v.z; dst[48] = v.w;
        }
        // --- stage vw (gathered): sVWf[h*20 + mc] ---
        if (t < 64) {
            int mc = t >> 2, hh = t & 3;
            int m = m0 + mc;
            int r = (m < N_) ? m : oc[m - N_];
            sVWf[hh*20 + mc] = g_VW[(size_t)(b*N_ + r)*H_ + h0 + hh];
        }
        // --- stage delta_pos: sDPf[c*320 + nn*20 + mc] ---
#pragma unroll
        for (int it = 0; it < 3; it++) {
            int idx = it*256 + t;                  // 768 slots
            int nn = idx / 48; int rem = idx - nn*48;
            int mc = rem / 3;  int c = rem - mc*3;
            sDPf[c*320 + nn*20 + mc] = dp[((size_t)(b*N_ + n0 + nn)*M_ + m0 + mc)*3 + c];
        }
        __syncthreads();

        // --- compute: two m-pairs (s*4+{0,1}) and (s*4+{2,3}) ---
        ull l2a = 0ull, l2b = 0ull;
#pragma unroll
        for (int d = 0; d < 16; d++) {
            float4 kf = sK4[h*65 + d*4 + s];       // floats h*260 + d*16 + s*4 ..+3
            l2a = fma2_(q2[d], pk2(kf.x, kf.y), l2a);
            l2b = fma2_(q2[d], pk2(kf.z, kf.w), l2b);
        }
        l2a = fma2_(pk2(cbias.x, cbias.y), L2E2, l2a);
        l2b = fma2_(pk2(cbias.z, cbias.w), L2E2, l2b);
        float a0, a1, b0, b1;
        upk2(a0, a1, l2a); upk2(b0, b1, l2b);
        ull p2a = pk2(ex2_(a0), ex2_(a1));
        ull p2b = pk2(ex2_(b0), ex2_(b1));
        den = add2_(den, p2a);
        den = add2_(den, p2b);
        float4 vwf = sVW4[h*5 + s];                // floats h*20 + s*4 ..+3
        ull pva = mul2_(p2a, pk2(vwf.x, vwf.y));
        ull pvb = mul2_(p2b, pk2(vwf.z, vwf.w));
        float4 dd0 = sDP4[0*80 + nr*5 + s];        // floats c*320 + nr*20 + s*4
        float4 dd1 = sDP4[1*80 + nr*5 + s];
        float4 dd2 = sDP4[2*80 + nr*5 + s];
        Ac0 = fma2_(pva, pk2(dd0.x, dd0.y), Ac0);
        Ac0 = fma2_(pvb, pk2(dd0.z, dd0.w), Ac0);
        Ac1 = fma2_(pva, pk2(dd1.x, dd1.y), Ac1);
        Ac1 = fma2_(pvb, pk2(dd1.z, dd1.w), Ac1);
        Ac2 = fma2_(pva, pk2(dd2.x, dd2.y), Ac2);
        Ac2 = fma2_(pvb, pk2(dd2.z, dd2.w), Ac2);
    }

    __syncthreads();
    {
        float x0, x1;
        upk2(x0, x1, den); scomb[s][h][nr][0] = x0 + x1;
        upk2(x0, x1, Ac0); scomb[s][h][nr][1] = x0 + x1;
        upk2(x0, x1, Ac1); scomb[s][h][nr][2] = x0 + x1;
        upk2(x0, x1, Ac2); scomb[s][h][nr][3] = x0 + x1;
    }
    __syncthreads();

    // reduce over s and write partials: 256 slots = (hh, nr, val)
    {
        int val = t & 3, rnr = (t >> 2) & 15, hh = t >> 6;
        float a = scomb[0][hh][rnr][val] + scomb[1][hh][rnr][val]
                + scomb[2][hh][rnr][val] + scomb[3][hh][rnr][val];
        int nn = n0 + rnr;
        g_part[(((size_t)(g*2 + ms)*2 + b)*N_ + nn)*16 + hh*4 + val] = a;
    }
}

// ---------------- kernel 5: final combine ----------------
__global__ __launch_bounds__(256) void final_kernel(float* __restrict__ out)
{
    int i = blockIdx.x*256 + threadIdx.x;   // 4 blocks -> 1024 = B*N
    int b = i >> 9, n = i & 511;
    float f0 = 0.f, f1 = 0.f, f2 = 0.f;
#pragma unroll 4
    for (int g = 0; g < 12; g++) {
#pragma unroll
        for (int hh = 0; hh < 4; hh++) {
            float4 v0 = *(const float4*)&g_part[(((size_t)(g*2+0)*2 + b)*N_ + n)*16 + hh*4];
            float4 v1 = *(const float4*)&g_part[(((size_t)(g*2+1)*2 + b)*N_ + n)*16 + hh*4];
            float inv = 1.0f / (v0.x + v1.x);
            f0 = fmaf(v0.y + v1.y, inv, f0);
            f1 = fmaf(v0.z + v1.z, inv, f1);
            f2 = fmaf(v0.w + v1.w, inv, f2);
        }
    }
    out[i*3+0] = f0; out[i*3+1] = f1; out[i*3+2] = f2;
}

// ---------------- launch ----------------
extern "C" void kernel_launch(void* const* d_in, const int* in_sizes, int n_in,
                              void* d_out, int out_size)
{
    const float* query = (const float*)d_in[0];
    const float* bias  = (const float*)d_in[1];
    const float* dp    = (const float*)d_in[2];
    const int*   oc    = (const int*)  d_in[3];
    const float* Wq    = (const float*)d_in[4];
    const float* bq    = (const float*)d_in[5];
    const float* Wk    = (const float*)d_in[6];
    const float* bk    = (const float*)d_in[7];
    const float* Wv    = (const float*)d_in[8];
    const float* bv    = (const float*)d_in[9];
    const float* wf    = (const float*)d_in[10];
    float* out = (float*)d_out;

    wveff_kernel<<<H_, E_>>>(Wv, bv, wf);
    qk_gemm<<<dim3(12, 16), 256>>>(query, Wq, bq, Wk, bk);
    vw_kernel<<<B_*N_, E_>>>(query);
    attn_kernel<<<dim3(12, 32, 4), 256>>>(bias, dp, oc);
    final_kernel<<<4, 256>>>(out);
}

// round 16
// speedup vs baseline: 1.2352x; 1.2352x over previous
#include <cuda_runtime.h>

#define B_    2
#define N_    512
#define E_    768
#define H_    48
#define D_    16
#define NEXP_ 256
#define M_    768
#define LOG2E 1.4426950408889634f

typedef unsigned long long ull;

__device__ __forceinline__ ull pk2(float lo, float hi){ ull r; asm("mov.b64 %0,{%1,%2};":"=l"(r):"f"(lo),"f"(hi)); return r; }
__device__ __forceinline__ void upk2(float&lo,float&hi,ull v){ asm("mov.b64 {%0,%1},%2;":"=f"(lo),"=f"(hi):"l"(v)); }
__device__ __forceinline__ ull fma2_(ull a, ull b, ull c){ ull d; asm("fma.rn.f32x2 %0,%1,%2,%3;":"=l"(d):"l"(a),"l"(b),"l"(c)); return d; }
__device__ __forceinline__ ull add2_(ull a, ull b){ ull d; asm("add.rn.f32x2 %0,%1,%2;":"=l"(d):"l"(a),"l"(b)); return d; }
__device__ __forceinline__ ull mul2_(ull a, ull b){ ull d; asm("mul.rn.f32x2 %0,%1,%2;":"=l"(d):"l"(a),"l"(b)); return d; }
__device__ __forceinline__ float ex2_(float x){ float r; asm("ex2.approx.f32 %0,%1;":"=f"(r):"f"(x)); return r; }

// ---------------- device scratch ----------------
__device__ float g_Q[B_*N_*E_];          // Q proj, pre-scaled by 0.25*log2e
__device__ float g_K[B_*N_*E_];          // K proj
__device__ float g_VW[B_*N_*H_];         // v . w_force per head  [row][48]
__device__ float g_Kx[B_*NEXP_*E_];      // pre-gathered K extension rows
__device__ float g_VWx[B_*NEXP_*H_];     // pre-gathered vw extension rows
__device__ float g_Wveff[H_*E_];
__device__ float g_beff[H_];
__device__ float g_part[12*2*B_*N_*16];  // [g][ms][b][n][hh][4]: den,A0,A1,A2

// ---------------- kernel 1: fold Wv with w_force ----------------
__global__ void wveff_kernel(const float* __restrict__ Wv,
                             const float* __restrict__ bv,
                             const float* __restrict__ wf)
{
    int h = blockIdx.x, e = threadIdx.x;
    float sv = 0.f;
#pragma unroll
    for (int dd = 0; dd < 16; dd++)
        sv = fmaf(wf[h*16+dd], Wv[(h*16+dd)*E_ + e], sv);
    g_Wveff[h*E_ + e] = sv;
    if (e == 0) {
        float bb = 0.f;
#pragma unroll
        for (int dd = 0; dd < 16; dd++)
            bb = fmaf(wf[h*16+dd], bv[h*16+dd], bb);
        g_beff[h] = bb;
    }
}

// ---------------- kernel 2: fused Q+K projection GEMM (PASSED, unchanged) ----------------
__global__ __launch_bounds__(256,2) void qk_gemm(
    const float* __restrict__ A,
    const float* __restrict__ Wq, const float* __restrict__ bq,
    const float* __restrict__ Wk, const float* __restrict__ bk)
{
    __shared__ ull   Asd[2][16*64];    // [k][row], duplicated (a,a)
    __shared__ float Bs[2][16*132];    // [k][col], pad 132

    int t  = threadIdx.x;
    int tx = t & 15, ty = t >> 4;
    int row0 = blockIdx.y * 64;
    int col0 = blockIdx.x * 128;

    const float* __restrict__ W; const float* __restrict__ bvec;
    float scale; float* C; int cb;
    if (col0 < E_) { W = Wq; bvec = bq; scale = 0.25f*LOG2E; C = g_Q; cb = col0; }
    else           { W = Wk; bvec = bk; scale = 1.0f;        C = g_K; cb = col0 - E_; }

    int arow = t >> 2;
    int akq  = (t & 3) * 4;
    const float* Aptr = A + (row0 + arow)*E_ + akq;
    int bc0 = t >> 2,        bk0 = (t & 3)*4;
    int bc1 = (256+t) >> 2,  bk1 = ((256+t) & 3)*4;
    const float* Bptr0 = W + (cb + bc0)*E_ + bk0;
    const float* Bptr1 = W + (cb + bc1)*E_ + bk1;

    ull acc[4][4];
#pragma unroll
    for (int r = 0; r < 4; r++)
#pragma unroll
        for (int j = 0; j < 4; j++) acc[r][j] = 0ull;

    {
        float4 va = *(const float4*)(Aptr);
        Asd[0][(akq+0)*64+arow] = pk2(va.x,va.x);
        Asd[0][(akq+1)*64+arow] = pk2(va.y,va.y);
        Asd[0][(akq+2)*64+arow] = pk2(va.z,va.z);
        Asd[0][(akq+3)*64+arow] = pk2(va.w,va.w);
        float4 vb = *(const float4*)(Bptr0);
        Bs[0][(bk0+0)*132+bc0] = vb.x; Bs[0][(bk0+1)*132+bc0] = vb.y;
        Bs[0][(bk0+2)*132+bc0] = vb.z; Bs[0][(bk0+3)*132+bc0] = vb.w;
        float4 vc = *(const float4*)(Bptr1);
        Bs[0][(bk1+0)*132+bc1] = vc.x; Bs[0][(bk1+1)*132+bc1] = vc.y;
        Bs[0][(bk1+2)*132+bc1] = vc.z; Bs[0][(bk1+3)*132+bc1] = vc.w;
    }
    __syncthreads();

    for (int s = 0; s < 48; s++) {
        int buf = s & 1;
        float4 pa, pb, pc;
        if (s < 47) {
            int k0 = (s+1)*16;
            pa = *(const float4*)(Aptr + k0);
            pb = *(const float4*)(Bptr0 + k0);
            pc = *(const float4*)(Bptr1 + k0);
        }
#pragma unroll
        for (int k = 0; k < 16; k++) {
            ull a2[4];
#pragma unroll
            for (int r = 0; r < 4; r++) a2[r] = Asd[buf][k*64 + ty*4 + r];
            const ull* bp = (const ull*)&Bs[buf][k*132];
            ull b2[4];
#pragma unroll
            for (int jp = 0; jp < 4; jp++) b2[jp] = bp[tx + 16*jp];
#pragma unroll
            for (int r = 0; r < 4; r++)
#pragma unroll
                for (int jp = 0; jp < 4; jp++)
                    acc[r][jp] = fma2_(a2[r], b2[jp], acc[r][jp]);
        }
        if (s < 47) {
            int nb = buf ^ 1;
            Asd[nb][(akq+0)*64+arow] = pk2(pa.x,pa.x);
            Asd[nb][(akq+1)*64+arow] = pk2(pa.y,pa.y);
            Asd[nb][(akq+2)*64+arow] = pk2(pa.z,pa.z);
            Asd[nb][(akq+3)*64+arow] = pk2(pa.w,pa.w);
            Bs[nb][(bk0+0)*132+bc0] = pb.x; Bs[nb][(bk0+1)*132+bc0] = pb.y;
            Bs[nb][(bk0+2)*132+bc0] = pb.z; Bs[nb][(bk0+3)*132+bc0] = pb.w;
            Bs[nb][(bk1+0)*132+bc1] = pc.x; Bs[nb][(bk1+1)*132+bc1] = pc.y;
            Bs[nb][(bk1+2)*132+bc1] = pc.z; Bs[nb][(bk1+3)*132+bc1] = pc.w;
        }
        __syncthreads();
    }

#pragma unroll
    for (int r = 0; r < 4; r++) {
        int row = row0 + ty*4 + r;
#pragma unroll
        for (int jp = 0; jp < 4; jp++) {
            int c0 = cb + 2*(tx + 16*jp);
            float v0, v1; upk2(v0, v1, acc[r][jp]);
            float2 o = make_float2(scale*(v0 + bvec[c0]), scale*(v1 + bvec[c0+1]));
            *(float2*)(C + row*E_ + c0) = o;
        }
    }
}

// ---------------- kernel 3: vw = query @ Wv_eff^T + b_eff (PASSED, unchanged) ----------------
__global__ __launch_bounds__(768) void vw_kernel(const float* __restrict__ query)
{
    __shared__ float qrow[E_];
    int row = blockIdx.x;
    qrow[threadIdx.x] = query[row*E_ + threadIdx.x];
    __syncthreads();
    int h = threadIdx.x >> 4, lane = threadIdx.x & 15;
    const float* __restrict__ wv = &g_Wveff[h*E_];
    float sacc = 0.f;
#pragma unroll 8
    for (int j = lane; j < E_; j += 16) sacc = fmaf(qrow[j], wv[j], sacc);
#pragma unroll
    for (int o = 8; o > 0; o >>= 1) sacc += __shfl_down_sync(0xffffffffu, sacc, o, 16);
    if (lane == 0) g_VW[row*H_ + h] = sacc + g_beff[h];
}

// ---------------- kernel 3b: pre-gather extension rows ----------------
__global__ __launch_bounds__(256) void gather_kernel(const int* __restrict__ outcell)
{
    int j = blockIdx.x & 255, b = blockIdx.x >> 8;
    int r = outcell[b*NEXP_ + j];
    int t = threadIdx.x;
    const float4* src = (const float4*)&g_K[(size_t)(b*N_ + r)*E_];
    float4* dst = (float4*)&g_Kx[(size_t)(b*NEXP_ + j)*E_];
    if (t < 192) {
        dst[t] = src[t];
    } else if (t < 240) {
        int c = t - 192;
        g_VWx[(size_t)(b*NEXP_ + j)*H_ + c] = g_VW[(size_t)(b*N_ + r)*H_ + c];
    }
}

// ---------------- kernel 4: fused attention (m-packed f32x2, pipelined, 1 barrier/chunk) ----------------
// grid (12 hg, 32 ntile(16 rows), b*2+ms).  256 threads: h=t&3, nr=(t>>2)&15, s=t>>6.
__global__ __launch_bounds__(256,2) void attn_kernel(
    const float* __restrict__ bias, const float* __restrict__ dp)
{
    __shared__ float4 sK4[2*260];        // per buf: [h][d][mc] floats, h-stride 260, d-stride 16
    __shared__ float4 sVW4[2*20];        // per buf: [h][mc], h-stride 20
    __shared__ float4 sDP4[2*240];       // per buf: [c][nn][mc], c-stride 320, nn-stride 20
    __shared__ float  scomb[4][4][16][4];// [s][h][nr][val]

    int t  = threadIdx.x;
    int h  = t & 3;
    int nr = (t >> 2) & 15;
    int s  = t >> 6;
    int g  = blockIdx.x;
    int h0 = g * 4;
    int n0 = blockIdx.y * 16;
    int bz = blockIdx.z;
    int b  = bz >> 1, ms = bz & 1;
    int n = n0 + nr;

    // Q duplicated in registers (loop-invariant). Pre-scaled by 0.25*log2e.
    ull q2[16];
    {
        const float4* qp = (const float4*)&g_Q[(size_t)(b*N_ + n)*E_ + (h0+h)*D_];
#pragma unroll
        for (int i = 0; i < 4; i++) {
            float4 v = qp[i];
            q2[4*i+0] = pk2(v.x,v.x); q2[4*i+1] = pk2(v.y,v.y);
            q2[4*i+2] = pk2(v.z,v.z); q2[4*i+3] = pk2(v.w,v.w);
        }
    }

    const float* bptr = bias + (size_t)(b*H_ + h0 + h)*(N_*M_) + (size_t)n*M_ + ms*384 + s*4;
    // staging roles
    int mcs = t >> 4, q4 = t & 15;
    int khh = q4 >> 2, kdg = (q4 & 3)*4;
    int vmc = t >> 2, vhh = t & 3;       // t<64 only
    int dnn = t >> 4, dmc = t & 15;
    const ull L2E2 = pk2(LOG2E, LOG2E);

    // per-buf float views
    float* sKf  = (float*)sK4;           // buf*1040
    float* sVWf = (float*)sVW4;          // buf*80
    float* sDPf = (float*)sDP4;          // buf*960

    float4 kReg; float vwReg = 0.f; float dR0, dR1, dR2;

#define LOADCH(CH) {                                                              \
        int m0_ = ms*384 + (CH)*16;                                               \
        int mK_ = m0_ + mcs;                                                      \
        const float* ks_ = (mK_ < N_) ? &g_K [(size_t)(b*N_    + mK_     )*E_]    \
                                      : &g_Kx[(size_t)(b*NEXP_ + mK_ - N_)*E_];   \
        kReg = *(const float4*)(ks_ + (h0+khh)*D_ + kdg);                         \
        if (t < 64) {                                                             \
            int mV_ = m0_ + vmc;                                                  \
            const float* vs_ = (mV_ < N_) ? &g_VW [(size_t)(b*N_    + mV_     )*H_] \
                                          : &g_VWx[(size_t)(b*NEXP_ + mV_ - N_)*H_]; \
            vwReg = vs_[h0 + vhh];                                                \
        }                                                                         \
        const float* dps_ = &dp[((size_t)(b*N_ + n0 + dnn)*M_ + m0_ + dmc)*3];    \
        dR0 = dps_[0]; dR1 = dps_[1]; dR2 = dps_[2];                              \
    }

#define STORECH(BUF) {                                                            \
        float* kd_ = &sKf[(BUF)*1040 + khh*260 + kdg*16 + mcs];                   \
        kd_[0] = kReg.x; kd_[16] = kReg.y; kd_[32] = kReg.z; kd_[48] = kReg.w;    \
        if (t < 64) sVWf[(BUF)*80 + vhh*20 + vmc] = vwReg;                        \
        float* dd_ = &sDPf[(BUF)*960 + dnn*20 + dmc];                             \
        dd_[0] = dR0; dd_[320] = dR1; dd_[640] = dR2;                             \
    }

    ull den = 0ull, Ac0 = 0ull, Ac1 = 0ull, Ac2 = 0ull;

    LOADCH(0);
    STORECH(0);
    float4 pb = *(const float4*)bptr;
    __syncthreads();

#pragma unroll 1
    for (int ch = 0; ch < 24; ch++) {
        int buf = ch & 1;
        if (ch < 23) {
            LOADCH(ch+1);
        }
        float4 cbias = pb;
        if (ch < 23) pb = *(const float4*)(bptr + (ch+1)*16);

        // --- compute from smem[buf]: two m-pairs (s*4+{0,1}) and (s*4+{2,3}) ---
        ull l2a = 0ull, l2b = 0ull;
#pragma unroll
        for (int d = 0; d < 16; d++) {
            float4 kf = sK4[buf*260 + h*65 + d*4 + s];
            l2a = fma2_(q2[d], pk2(kf.x, kf.y), l2a);
            l2b = fma2_(q2[d], pk2(kf.z, kf.w), l2b);
        }
        l2a = fma2_(pk2(cbias.x, cbias.y), L2E2, l2a);
        l2b = fma2_(pk2(cbias.z, cbias.w), L2E2, l2b);
        float a0, a1, b0, b1;
        upk2(a0, a1, l2a); upk2(b0, b1, l2b);
        ull p2a = pk2(ex2_(a0), ex2_(a1));
        ull p2b = pk2(ex2_(b0), ex2_(b1));
        den = add2_(den, p2a);
        den = add2_(den, p2b);
        float4 vwf = sVW4[buf*20 + h*5 + s];
        ull pva = mul2_(p2a, pk2(vwf.x, vwf.y));
        ull pvb = mul2_(p2b, pk2(vwf.z, vwf.w));
        float4 dd0 = sDP4[buf*240 + 0*80 + nr*5 + s];
        float4 dd1 = sDP4[buf*240 + 1*80 + nr*5 + s];
        float4 dd2 = sDP4[buf*240 + 2*80 + nr*5 + s];
        Ac0 = fma2_(pva, pk2(dd0.x, dd0.y), Ac0);
        Ac0 = fma2_(pvb, pk2(dd0.z, dd0.w), Ac0);
        Ac1 = fma2_(pva, pk2(dd1.x, dd1.y), Ac1);
        Ac1 = fma2_(pvb, pk2(dd1.z, dd1.w), Ac1);
        Ac2 = fma2_(pva, pk2(dd2.x, dd2.y), Ac2);
        Ac2 = fma2_(pvb, pk2(dd2.z, dd2.w), Ac2);

        if (ch < 23) {
            STORECH(buf ^ 1);
        }
        __syncthreads();
    }

    {
        float x0, x1;
        upk2(x0, x1, den); scomb[s][h][nr][0] = x0 + x1;
        upk2(x0, x1, Ac0); scomb[s][h][nr][1] = x0 + x1;
        upk2(x0, x1, Ac1); scomb[s][h][nr][2] = x0 + x1;
        upk2(x0, x1, Ac2); scomb[s][h][nr][3] = x0 + x1;
    }
    __syncthreads();

    // reduce over s and write partials: 256 slots = (hh, nr, val)
    {
        int val = t & 3, rnr = (t >> 2) & 15, hh = t >> 6;
        float a = scomb[0][hh][rnr][val] + scomb[1][hh][rnr][val]
                + scomb[2][hh][rnr][val] + scomb[3][hh][rnr][val];
        int nn = n0 + rnr;
        g_part[(((size_t)(g*2 + ms)*2 + b)*N_ + nn)*16 + hh*4 + val] = a;
    }
#undef LOADCH
#undef STORECH
}

// ---------------- kernel 5: final combine ----------------
__global__ __launch_bounds__(256) void final_kernel(float* __restrict__ out)
{
    int i = blockIdx.x*256 + threadIdx.x;   // 4 blocks -> 1024 = B*N
    int b = i >> 9, n = i & 511;
    float f0 = 0.f, f1 = 0.f, f2 = 0.f;
#pragma unroll 4
    for (int g = 0; g < 12; g++) {
#pragma unroll
        for (int hh = 0; hh < 4; hh++) {
            float4 v0 = *(const float4*)&g_part[(((size_t)(g*2+0)*2 + b)*N_ + n)*16 + hh*4];
            float4 v1 = *(const float4*)&g_part[(((size_t)(g*2+1)*2 + b)*N_ + n)*16 + hh*4];
            float inv = 1.0f / (v0.x + v1.x);
            f0 = fmaf(v0.y + v1.y, inv, f0);
            f1 = fmaf(v0.z + v1.z, inv, f1);
            f2 = fmaf(v0.w + v1.w, inv, f2);
        }
    }
    out[i*3+0] = f0; out[i*3+1] = f1; out[i*3+2] = f2;
}

// ---------------- launch ----------------
extern "C" void kernel_launch(void* const* d_in, const int* in_sizes, int n_in,
                              void* d_out, int out_size)
{
    const float* query = (const float*)d_in[0];
    const float* bias  = (const float*)d_in[1];
    const float* dp    = (const float*)d_in[2];
    const int*   oc    = (const int*)  d_in[3];
    const float* Wq    = (const float*)d_in[4];
    const float* bq    = (const float*)d_in[5];
    const float* Wk    = (const float*)d_in[6];
    const float* bk    = (const float*)d_in[7];
    const float* Wv    = (const float*)d_in[8];
    const float* bv    = (const float*)d_in[9];
    const float* wf    = (const float*)d_in[10];
    float* out = (float*)d_out;

    wveff_kernel<<<H_, E_>>>(Wv, bv, wf);
    qk_gemm<<<dim3(12, 16), 256>>>(query, Wq, bq, Wk, bk);
    vw_kernel<<<B_*N_, E_>>>(query);
    gather_kernel<<<B_*NEXP_, 256>>>(oc);
    attn_kernel<<<dim3(12, 32, 4), 256>>>(bias, dp);
    final_kernel<<<4, 256>>>(out);
}

// round 17
// speedup vs baseline: 1.5550x; 1.2590x over previous
#include <cuda_runtime.h>

#define B_    2
#define N_    512
#define E_    768
#define H_    48
#define D_    16
#define NEXP_ 256
#define M_    768
#define LOG2E 1.4426950408889634f

typedef unsigned long long ull;

__device__ __forceinline__ ull pk2(float lo, float hi){ ull r; asm("mov.b64 %0,{%1,%2};":"=l"(r):"f"(lo),"f"(hi)); return r; }
__device__ __forceinline__ void upk2(float&lo,float&hi,ull v){ asm("mov.b64 {%0,%1},%2;":"=f"(lo),"=f"(hi):"l"(v)); }
__device__ __forceinline__ ull fma2_(ull a, ull b, ull c){ ull d; asm("fma.rn.f32x2 %0,%1,%2,%3;":"=l"(d):"l"(a),"l"(b),"l"(c)); return d; }
__device__ __forceinline__ ull add2_(ull a, ull b){ ull d; asm("add.rn.f32x2 %0,%1,%2;":"=l"(d):"l"(a),"l"(b)); return d; }
__device__ __forceinline__ ull mul2_(ull a, ull b){ ull d; asm("mul.rn.f32x2 %0,%1,%2;":"=l"(d):"l"(a),"l"(b)); return d; }
__device__ __forceinline__ float ex2_(float x){ float r; asm("ex2.approx.f32 %0,%1;":"=f"(r):"f"(x)); return r; }

// ---------------- device scratch ----------------
__device__ float g_Q[B_*N_*E_];          // Q proj, pre-scaled by 0.25*log2e
__device__ float g_K[B_*N_*E_];          // K proj
__device__ float g_VW[B_*N_*H_];         // v . w_force per head
__device__ float g_Kx[B_*NEXP_*E_];      // pre-gathered K extension rows
__device__ float g_VWx[B_*NEXP_*H_];     // pre-gathered vw extension rows
__device__ float g_Wveff[H_*E_];
__device__ float g_beff[H_];
__device__ float g_part[12*2*B_*N_*16];  // [g][ms][b][n][hh][4]: den,A0,A1,A2

// ---------------- kernel 1: fold Wv with w_force ----------------
__global__ void wveff_kernel(const float* __restrict__ Wv,
                             const float* __restrict__ bv,
                             const float* __restrict__ wf)
{
    int h = blockIdx.x, e = threadIdx.x;
    float sv = 0.f;
#pragma unroll
    for (int dd = 0; dd < 16; dd++)
        sv = fmaf(wf[h*16+dd], Wv[(h*16+dd)*E_ + e], sv);
    g_Wveff[h*E_ + e] = sv;
    if (e == 0) {
        float bb = 0.f;
#pragma unroll
        for (int dd = 0; dd < 16; dd++)
            bb = fmaf(wf[h*16+dd], bv[h*16+dd], bb);
        g_beff[h] = bb;
    }
}

// ---------------- kernel 2: Q+K projection GEMM, 64x64 tiles, 384 blocks ----------------
// 128 threads, micro 4 rows x 4 colpairs (f32x2), double-buffered.
__global__ __launch_bounds__(128,5) void qk_gemm(
    const float* __restrict__ A,
    const float* __restrict__ Wq, const float* __restrict__ bq,
    const float* __restrict__ Wk, const float* __restrict__ bk)
{
    __shared__ ulonglong2 AsdV[2][512];   // ull view: [k][row] duplicated (a,a), 16x64 per buf
    __shared__ ull        BsU[2][544];    // float view: [k][col] stride 68, 16x64 per buf

    ull*   AsdU = (ull*)AsdV;             // buf*512 ulonglong2 = buf*1024 ull
    float* BsF  = (float*)BsU;            // buf*1088 floats

    int t  = threadIdx.x;
    int tx = t & 7, ty = t >> 3;          // tx: 8 colpair groups, ty: 16 row groups
    int row0 = blockIdx.y * 64;
    int col0 = blockIdx.x * 64;

    const float* __restrict__ W; const float* __restrict__ bvec;
    float scale; float* C; int cb;
    if (col0 < E_) { W = Wq; bvec = bq; scale = 0.25f*LOG2E; C = g_Q; cb = col0; }
    else           { W = Wk; bvec = bk; scale = 1.0f;        C = g_K; cb = col0 - E_; }

    int srow = t >> 1, skq = (t & 1) * 8;
    const float* Ap = A + (size_t)(row0 + srow)*E_ + skq;
    const float* Wp = W + (size_t)(cb   + srow)*E_ + skq;

    ull acc[4][4];
#pragma unroll
    for (int r = 0; r < 4; r++)
#pragma unroll
        for (int j = 0; j < 4; j++) acc[r][j] = 0ull;

    // prologue: stage k0=0 into buf 0
    {
        float4 a0 = *(const float4*)(Ap), a1 = *(const float4*)(Ap+4);
        float4 w0 = *(const float4*)(Wp), w1 = *(const float4*)(Wp+4);
        float av[8] = {a0.x,a0.y,a0.z,a0.w,a1.x,a1.y,a1.z,a1.w};
        float wv[8] = {w0.x,w0.y,w0.z,w0.w,w1.x,w1.y,w1.z,w1.w};
#pragma unroll
        for (int j = 0; j < 8; j++) {
            AsdU[(skq+j)*64 + srow] = pk2(av[j], av[j]);
            BsF [(skq+j)*68 + srow] = wv[j];
        }
    }
    __syncthreads();

#pragma unroll 1
    for (int s = 0; s < 48; s++) {
        int buf = s & 1;
        float4 a0, a1, w0, w1;
        if (s < 47) {
            int k0 = (s+1)*16;
            a0 = *(const float4*)(Ap + k0); a1 = *(const float4*)(Ap + k0 + 4);
            w0 = *(const float4*)(Wp + k0); w1 = *(const float4*)(Wp + k0 + 4);
        }
#pragma unroll
        for (int k = 0; k < 16; k++) {
            ulonglong2 aa = AsdV[buf][k*32 + ty*2];
            ulonglong2 ab = AsdV[buf][k*32 + ty*2 + 1];
            ull a2[4] = {aa.x, aa.y, ab.x, ab.y};
            ull b2[4];
#pragma unroll
            for (int jp = 0; jp < 4; jp++)
                b2[jp] = BsU[buf][k*34 + tx + 8*jp];
#pragma unroll
            for (int r = 0; r < 4; r++)
#pragma unroll
                for (int jp = 0; jp < 4; jp++)
                    acc[r][jp] = fma2_(a2[r], b2[jp], acc[r][jp]);
        }
        if (s < 47) {
            int nb = buf ^ 1;
            float av[8] = {a0.x,a0.y,a0.z,a0.w,a1.x,a1.y,a1.z,a1.w};
            float wv[8] = {w0.x,w0.y,w0.z,w0.w,w1.x,w1.y,w1.z,w1.w};
            ull*   au = AsdU + nb*1024;
            float* bf = BsF  + nb*1088;
#pragma unroll
            for (int j = 0; j < 8; j++) {
                au[(skq+j)*64 + srow] = pk2(av[j], av[j]);
                bf[(skq+j)*68 + srow] = wv[j];
            }
        }
        __syncthreads();
    }

#pragma unroll
    for (int r = 0; r < 4; r++) {
        int row = row0 + ty*4 + r;
#pragma unroll
        for (int jp = 0; jp < 4; jp++) {
            int col = 2*(tx + 8*jp);
            float v0, v1; upk2(v0, v1, acc[r][jp]);
            float2 o = make_float2(scale*(v0 + bvec[col]), scale*(v1 + bvec[col+1]));
            *(float2*)(C + (size_t)row*E_ + cb + col) = o;
        }
    }
}

// ---------------- kernel 3: vw = query @ Wv_eff^T + b_eff (PASSED, unchanged) ----------------
__global__ __launch_bounds__(768) void vw_kernel(const float* __restrict__ query)
{
    __shared__ float qrow[E_];
    int row = blockIdx.x;
    qrow[threadIdx.x] = query[row*E_ + threadIdx.x];
    __syncthreads();
    int h = threadIdx.x >> 4, lane = threadIdx.x & 15;
    const float* __restrict__ wv = &g_Wveff[h*E_];
    float sacc = 0.f;
#pragma unroll 8
    for (int j = lane; j < E_; j += 16) sacc = fmaf(qrow[j], wv[j], sacc);
#pragma unroll
    for (int o = 8; o > 0; o >>= 1) sacc += __shfl_down_sync(0xffffffffu, sacc, o, 16);
    if (lane == 0) g_VW[row*H_ + h] = sacc + g_beff[h];
}

// ---------------- kernel 3b: pre-gather extension rows (PASSED, unchanged) ----------------
__global__ __launch_bounds__(256) void gather_kernel(const int* __restrict__ outcell)
{
    int j = blockIdx.x & 255, b = blockIdx.x >> 8;
    int r = outcell[b*NEXP_ + j];
    int t = threadIdx.x;
    const float4* src = (const float4*)&g_K[(size_t)(b*N_ + r)*E_];
    float4* dst = (float4*)&g_Kx[(size_t)(b*NEXP_ + j)*E_];
    if (t < 192) {
        dst[t] = src[t];
    } else if (t < 240) {
        int c = t - 192;
        g_VWx[(size_t)(b*NEXP_ + j)*H_ + c] = g_VW[(size_t)(b*N_ + r)*H_ + c];
    }
}

// ---------------- kernel 4: fused attention (n-rowpair-packed f32x2, pipelined) ----------------
// grid (12 hg, 16 ntile(32 rows), b*2+ms).  256 threads: h=t&3, nrp=(t>>2)&15, s=t>>6.
// Thread: rows (2*nrp, 2*nrp+1) packed in f32x2 lanes, 4 m-cols per 16-chunk; 24 chunks.
__global__ __launch_bounds__(256,2) void attn_kernel(
    const float* __restrict__ bias, const float* __restrict__ dp)
{
    __shared__ float4 sK4[2*260];        // per buf floats: [h][d][mc], h-stride 260, d-stride 16
    __shared__ float4 sVW4[2*20];        // per buf floats: [h][mc], h-stride 20
    __shared__ float4 sDP4[2*480];       // per buf floats: [c][nn][mc], c-stride 640, nn-stride 20
    __shared__ float  scomb[4][4][32][4];// [s][h][row][val]

    int t   = threadIdx.x;
    int h   = t & 3;
    int nrp = (t >> 2) & 15;
    int s   = t >> 6;
    int g   = blockIdx.x;
    int h0  = g * 4;
    int n0  = blockIdx.y * 32;
    int bz  = blockIdx.z;
    int b   = bz >> 1, ms = bz & 1;
    int r0  = n0 + 2*nrp;                // this thread's row pair: r0, r0+1

    // Q rowpair packed (row, row+1), invariant. Pre-scaled by 0.25*log2e.
    ull q2[16];
    {
        const float* q0 = &g_Q[(size_t)(b*N_ + r0)*E_ + (h0+h)*D_];
        const float* q1 = q0 + E_;
#pragma unroll
        for (int i = 0; i < 4; i++) {
            float4 v0 = *(const float4*)(q0 + 4*i);
            float4 v1 = *(const float4*)(q1 + 4*i);
            q2[4*i+0] = pk2(v0.x,v1.x); q2[4*i+1] = pk2(v0.y,v1.y);
            q2[4*i+2] = pk2(v0.z,v1.z); q2[4*i+3] = pk2(v0.w,v1.w);
        }
    }

    const float* bptr = bias + (size_t)(b*H_ + h0 + h)*(N_*M_) + (size_t)r0*M_ + ms*384 + s*4;
    // staging roles
    int mcs = t >> 4, q4 = t & 15;
    int khh = q4 >> 2, kdg = (q4 & 3)*4;
    int vmc = t >> 2, vhh = t & 3;       // t<64 only
    int dnn = t >> 4, dmc = t & 15;      // dp: rows dnn, dnn+16
    const ull L2E2 = pk2(LOG2E, LOG2E);

    float* sKf  = (float*)sK4;           // buf*1040
    float* sVWf = (float*)sVW4;          // buf*80
    float* sDPf = (float*)sDP4;          // buf*1920

    float4 kReg; float vwReg = 0.f;
    float dR[2][3];

#define LOADCH(CH) {                                                              \
        int m0_ = ms*384 + (CH)*16;                                               \
        int mK_ = m0_ + mcs;                                                      \
        const float* ks_ = (mK_ < N_) ? &g_K [(size_t)(b*N_    + mK_     )*E_]    \
                                      : &g_Kx[(size_t)(b*NEXP_ + mK_ - N_)*E_];   \
        kReg = *(const float4*)(ks_ + (h0+khh)*D_ + kdg);                         \
        if (t < 64) {                                                             \
            int mV_ = m0_ + vmc;                                                  \
            const float* vs_ = (mV_ < N_) ? &g_VW [(size_t)(b*N_    + mV_     )*H_] \
                                          : &g_VWx[(size_t)(b*NEXP_ + mV_ - N_)*H_]; \
            vwReg = vs_[h0 + vhh];                                                \
        }                                                                         \
        _Pragma("unroll")                                                         \
        for (int rep = 0; rep < 2; rep++) {                                       \
            int nn_ = dnn + 16*rep;                                               \
            const float* dps_ = &dp[((size_t)(b*N_ + n0 + nn_)*M_ + m0_ + dmc)*3];\
            dR[rep][0] = dps_[0]; dR[rep][1] = dps_[1]; dR[rep][2] = dps_[2];     \
        }                                                                         \
    }

#define STORECH(BUF) {                                                            \
        float* kd_ = &sKf[(BUF)*1040 + khh*260 + kdg*16 + mcs];                   \
        kd_[0] = kReg.x; kd_[16] = kReg.y; kd_[32] = kReg.z; kd_[48] = kReg.w;    \
        if (t < 64) sVWf[(BUF)*80 + vhh*20 + vmc] = vwReg;                        \
        _Pragma("unroll")                                                         \
        for (int rep = 0; rep < 2; rep++) {                                       \
            int nn_ = dnn + 16*rep;                                               \
            float* dd_ = &sDPf[(BUF)*1920 + nn_*20 + dmc];                        \
            dd_[0] = dR[rep][0]; dd_[640] = dR[rep][1]; dd_[1280] = dR[rep][2];   \
        }                                                                         \
    }

    ull den = 0ull, Ac0 = 0ull, Ac1 = 0ull, Ac2 = 0ull;

    LOADCH(0);
    STORECH(0);
    float4 pb0 = *(const float4*)bptr;
    float4 pb1 = *(const float4*)(bptr + M_);
    __syncthreads();

#pragma unroll 1
    for (int ch = 0; ch < 24; ch++) {
        int buf = ch & 1;
        if (ch < 23) { LOADCH(ch+1); }
        float4 cb0 = pb0, cb1 = pb1;
        if (ch < 23) {
            pb0 = *(const float4*)(bptr + (ch+1)*16);
            pb1 = *(const float4*)(bptr + (ch+1)*16 + M_);
        }

        // --- compute from smem[buf]: 4 m-columns, rows packed in lanes ---
        ull l0 = 0ull, l1 = 0ull, l2v = 0ull, l3 = 0ull;
#pragma unroll
        for (int d = 0; d < 16; d++) {
            float4 kf = sK4[buf*260 + h*65 + d*4 + s];
            l0  = fma2_(q2[d], pk2(kf.x,kf.x), l0);
            l1  = fma2_(q2[d], pk2(kf.y,kf.y), l1);
            l2v = fma2_(q2[d], pk2(kf.z,kf.z), l2v);
            l3  = fma2_(q2[d], pk2(kf.w,kf.w), l3);
        }
        l0  = fma2_(pk2(cb0.x, cb1.x), L2E2, l0);
        l1  = fma2_(pk2(cb0.y, cb1.y), L2E2, l1);
        l2v = fma2_(pk2(cb0.z, cb1.z), L2E2, l2v);
        l3  = fma2_(pk2(cb0.w, cb1.w), L2E2, l3);
        float xa, xb;
        upk2(xa, xb, l0);  ull p0 = pk2(ex2_(xa), ex2_(xb));
        upk2(xa, xb, l1);  ull p1 = pk2(ex2_(xa), ex2_(xb));
        upk2(xa, xb, l2v); ull p2 = pk2(ex2_(xa), ex2_(xb));
        upk2(xa, xb, l3);  ull p3 = pk2(ex2_(xa), ex2_(xb));
        ull s01 = add2_(p0, p1), s23 = add2_(p2, p3);
        den = add2_(den, add2_(s01, s23));
        float4 vwf = sVW4[buf*20 + h*5 + s];
        ull pv0 = mul2_(p0, pk2(vwf.x, vwf.x));
        ull pv1 = mul2_(p1, pk2(vwf.y, vwf.y));
        ull pv2 = mul2_(p2, pk2(vwf.z, vwf.z));
        ull pv3 = mul2_(p3, pk2(vwf.w, vwf.w));
#pragma unroll
        for (int c = 0; c < 3; c++) {
            int base = buf*480 + c*160 + nrp*10 + s;
            float4 dA = sDP4[base];        // row r0
            float4 dB = sDP4[base + 5];    // row r0+1
            ull a = (c==0) ? Ac0 : (c==1) ? Ac1 : Ac2;
            a = fma2_(pv0, pk2(dA.x, dB.x), a);
            a = fma2_(pv1, pk2(dA.y, dB.y), a);
            a = fma2_(pv2, pk2(dA.z, dB.z), a);
            a = fma2_(pv3, pk2(dA.w, dB.w), a);
            if (c==0) Ac0 = a; else if (c==1) Ac1 = a; else Ac2 = a;
        }

        if (ch < 23) { STORECH(buf ^ 1); }
        __syncthreads();
    }

    {
        float x0, x1;
        upk2(x0, x1, den); scomb[s][h][2*nrp][0] = x0; scomb[s][h][2*nrp+1][0] = x1;
        upk2(x0, x1, Ac0); scomb[s][h][2*nrp][1] = x0; scomb[s][h][2*nrp+1][1] = x1;
        upk2(x0, x1, Ac1); scomb[s][h][2*nrp][2] = x0; scomb[s][h][2*nrp+1][2] = x1;
        upk2(x0, x1, Ac2); scomb[s][h][2*nrp][3] = x0; scomb[s][h][2*nrp+1][3] = x1;
    }
    __syncthreads();

    // reduce over s and write partials: 512 slots = (hh, row, val)
#pragma unroll
    for (int rep = 0; rep < 2; rep++) {
        int slot = rep*256 + t;
        int val = slot & 3, row = (slot >> 2) & 31, hh = slot >> 7;
        float a = scomb[0][hh][row][val] + scomb[1][hh][row][val]
                + scomb[2][hh][row][val] + scomb[3][hh][row][val];
        g_part[(((size_t)(g*2 + ms)*2 + b)*N_ + n0 + row)*16 + hh*4 + val] = a;
    }
#undef LOADCH
#undef STORECH
}

// ---------------- kernel 5: final combine ----------------
__global__ __launch_bounds__(256) void final_kernel(float* __restrict__ out)
{
    int i = blockIdx.x*256 + threadIdx.x;   // 4 blocks -> 1024 = B*N
    int b = i >> 9, n = i & 511;
    float f0 = 0.f, f1 = 0.f, f2 = 0.f;
#pragma unroll 4
    for (int g = 0; g < 12; g++) {
#pragma unroll
        for (int hh = 0; hh < 4; hh++) {
            float4 v0 = *(const float4*)&g_part[(((size_t)(g*2+0)*2 + b)*N_ + n)*16 + hh*4];
            float4 v1 = *(const float4*)&g_part[(((size_t)(g*2+1)*2 + b)*N_ + n)*16 + hh*4];
            float inv = 1.0f / (v0.x + v1.x);
            f0 = fmaf(v0.y + v1.y, inv, f0);
            f1 = fmaf(v0.z + v1.z, inv, f1);
            f2 = fmaf(v0.w + v1.w, inv, f2);
        }
    }
    out[i*3+0] = f0; out[i*3+1] = f1; out[i*3+2] = f2;
}

// ---------------- launch ----------------
extern "C" void kernel_launch(void* const* d_in, const int* in_sizes, int n_in,
                              void* d_out, int out_size)
{
    const float* query = (const float*)d_in[0];
    const float* bias  = (const float*)d_in[1];
    const float* dp    = (const float*)d_in[2];
    const int*   oc    = (const int*)  d_in[3];
    const float* Wq    = (const float*)d_in[4];
    const float* bq    = (const float*)d_in[5];
    const float* Wk    = (const float*)d_in[6];
    const float* bk    = (const float*)d_in[7];
    const float* Wv    = (const float*)d_in[8];
    const float* bv    = (const float*)d_in[9];
    const float* wf    = (const float*)d_in[10];
    float* out = (float*)d_out;

    wveff_kernel<<<H_, E_>>>(Wv, bv, wf);
    qk_gemm<<<dim3(24, 16), 128>>>(query, Wq, bq, Wk, bk);
    vw_kernel<<<B_*N_, E_>>>(query);
    gather_kernel<<<B_*NEXP_, 256>>>(oc);
    attn_kernel<<<dim3(12, 16, 4), 256>>>(bias, dp);
    final_kernel<<<4, 256>>>(out);
}